// round 1
// baseline (speedup 1.0000x reference)
#include <cuda_runtime.h>
#include <cstdint>

// ---------------------------------------------------------------------------
// WindowAttention fused kernel (one CTA per window), TF32 mma.sync
//   x:[4096,49,256]  qkv_w:[256,768]  proj_w:[256,256]  proj_b:[256]
//   bias_table:[169,8]  rel_idx:[49,49] int32   out:[4096,49,256] fp32
// ---------------------------------------------------------------------------

constexpr int NTOK = 49;
constexpr int DIMC = 256;
constexpr int NH   = 8;
constexpr int MP   = 64;   // padded token rows

// smem strides (floats). Chosen so every mma fragment LDS is conflict-free:
//   A-style pattern wants stride % 32 == 4 ; B-style wants stride % 32 == 8
constexpr int SX  = 260;   // x          (A operand)        %32==4
constexpr int SW1 = 104;   // qkv W chunk(B operand)        %32==8
constexpr int SWP = 264;   // proj W chunk(B operand)       %32==8
constexpr int SQ  = 36;    // q / O_h    (A operand)        %32==4
constexpr int SK  = 36;    // k          (B via row access) %32==4
constexpr int SV  = 40;    // v          (B operand)        %32==8
constexpr int SA  = 68;    // scores/probs (A operand)      %32==4

constexpr int OFF_X  = 0;
constexpr int OFF_W  = OFF_X  + MP * SX;        // 16640
constexpr int OFF_Q  = OFF_W  + 8448;           // max(64*104, 32*264)=8448
constexpr int OFF_K  = OFF_Q  + MP * SQ;
constexpr int OFF_V  = OFF_K  + MP * SK;
constexpr int OFF_A  = OFF_V  + MP * SV;
constexpr int OFF_BT = OFF_A  + MP * SA;        // bias_table 169*8
constexpr int OFF_PB = OFF_BT + 169 * NH;       // proj_b 256
constexpr int FLOATS = OFF_PB + 256;
constexpr int SMEM_BYTES = FLOATS * 4 + 2432;   // + rel_idx as uint8 (2401, padded)

__device__ __forceinline__ float tf32r(float x) {
    uint32_t u;
    asm("cvt.rna.tf32.f32 %0, %1;" : "=r"(u) : "f"(x));
    return __uint_as_float(u);
}

__device__ __forceinline__ void mma8(float c[4],
                                     uint32_t a0, uint32_t a1, uint32_t a2, uint32_t a3,
                                     uint32_t b0, uint32_t b1) {
    asm volatile(
        "mma.sync.aligned.m16n8k8.row.col.f32.tf32.tf32.f32 "
        "{%0,%1,%2,%3}, {%4,%5,%6,%7}, {%8,%9}, {%0,%1,%2,%3};"
        : "+f"(c[0]), "+f"(c[1]), "+f"(c[2]), "+f"(c[3])
        : "r"(a0), "r"(a1), "r"(a2), "r"(a3), "r"(b0), "r"(b1));
}

__global__ void __launch_bounds__(256, 1)
win_attn_kernel(const float* __restrict__ x,
                const float* __restrict__ qkv_w,
                const float* __restrict__ proj_w,
                const float* __restrict__ proj_b,
                const float* __restrict__ bias_table,
                const int*   __restrict__ rel_idx,
                float*       __restrict__ out) {
    extern __shared__ float sm[];
    float* s_x  = sm + OFF_X;
    float* s_w  = sm + OFF_W;
    float* s_q  = sm + OFF_Q;
    float* s_k  = sm + OFF_K;
    float* s_v  = sm + OFF_V;
    float* s_at = sm + OFF_A;
    float* s_bt = sm + OFF_BT;
    float* s_pb = sm + OFF_PB;
    unsigned char* s_ri = (unsigned char*)(sm + FLOATS);

    const int tid  = threadIdx.x;
    const int w    = tid >> 5;
    const int lane = tid & 31;
    const int g    = lane >> 2;   // mma group id (0..7)
    const int tg   = lane & 3;    // thread-in-group (0..3)
    const int b    = blockIdx.x;

    const int m   = (w & 3) * 16; // warp's M tile row base
    const int grp = w >> 2;       // warp half (0/1)

    // ---- init loads: x window -> s_x (tf32-rounded, rows 49..63 zero) ----
    {
        const float4* x4 = (const float4*)(x + (size_t)b * (NTOK * DIMC));
        #pragma unroll
        for (int i = 0; i < 16; i++) {
            int idx = tid + i * 256;          // 0..4095 == 64 rows * 64 float4
            int r = idx >> 6, c4 = idx & 63;
            float4 v = make_float4(0.f, 0.f, 0.f, 0.f);
            if (idx < 3136) v = x4[idx];      // 49*64
            float4 o;
            o.x = tf32r(v.x); o.y = tf32r(v.y); o.z = tf32r(v.z); o.w = tf32r(v.w);
            *(float4*)(s_x + r * SX + c4 * 4) = o;
        }
        for (int i = tid; i < 2401; i += 256) s_ri[i] = (unsigned char)rel_idx[i];
        for (int i = tid; i < 169 * NH; i += 256) s_bt[i] = bias_table[i];
        if (tid < 256) s_pb[tid] = proj_b[tid];
    }

    // persistent proj accumulators: warp covers rows m..m+15, cols grp*128..+127
    float facc[16][4];
    #pragma unroll
    for (int j = 0; j < 16; j++) {
        facc[j][0] = 0.f; facc[j][1] = 0.f; facc[j][2] = 0.f; facc[j][3] = 0.f;
    }

    for (int h = 0; h < NH; h++) {
        // ================= GEMM1: qkv_h[64,96] = x[64,256] @ W1_h =========
        float acc1[6][4];
        #pragma unroll
        for (int nt = 0; nt < 6; nt++) {
            acc1[nt][0] = 0.f; acc1[nt][1] = 0.f; acc1[nt][2] = 0.f; acc1[nt][3] = 0.f;
        }
        const int nb1 = grp * 48;
        for (int kc = 0; kc < 4; kc++) {
            __syncthreads();   // protect s_w (and s_q from prev head's proj)
            // stage W1 chunk [64 x 96] into s_w (tf32-rounded)
            #pragma unroll
            for (int i = 0; i < 6; i++) {
                int idx  = tid + i * 256;     // 0..1535 float4
                int r    = idx / 24;
                int c4   = idx - r * 24;
                int sect = c4 >> 3;           // 0=q 1=k 2=v
                int cc   = (c4 & 7) << 2;
                const float4 v = *(const float4*)(qkv_w +
                    (size_t)(kc * 64 + r) * 768 + sect * 256 + h * 32 + cc);
                float4 o;
                o.x = tf32r(v.x); o.y = tf32r(v.y); o.z = tf32r(v.z); o.w = tf32r(v.w);
                *(float4*)(s_w + r * SW1 + sect * 32 + cc) = o;
            }
            __syncthreads();
            #pragma unroll
            for (int kk = 0; kk < 8; kk++) {
                const int ks = kk * 8;
                const int ac = kc * 64 + ks;
                uint32_t a0 = __float_as_uint(s_x[(m + g)     * SX + ac + tg]);
                uint32_t a1 = __float_as_uint(s_x[(m + g + 8) * SX + ac + tg]);
                uint32_t a2 = __float_as_uint(s_x[(m + g)     * SX + ac + tg + 4]);
                uint32_t a3 = __float_as_uint(s_x[(m + g + 8) * SX + ac + tg + 4]);
                #pragma unroll
                for (int nt = 0; nt < 6; nt++) {
                    const int n = nb1 + nt * 8 + g;
                    uint32_t b0 = __float_as_uint(s_w[(ks + tg)     * SW1 + n]);
                    uint32_t b1 = __float_as_uint(s_w[(ks + tg + 4) * SW1 + n]);
                    mma8(acc1[nt], a0, a1, a2, a3, b0, b1);
                }
            }
        }
        // store q (scaled), k, v  (tf32-rounded)
        {
            const float scale = 0.17677669529663687f; // 1/sqrt(32)
            #pragma unroll
            for (int nt = 0; nt < 6; nt++) {
                int col  = nb1 + nt * 8 + 2 * tg;
                int sect = col >> 5;
                int cl   = col & 31;
                int r0 = m + g, r1 = m + g + 8;
                if (sect == 0) {
                    s_q[r0 * SQ + cl]     = tf32r(acc1[nt][0] * scale);
                    s_q[r0 * SQ + cl + 1] = tf32r(acc1[nt][1] * scale);
                    s_q[r1 * SQ + cl]     = tf32r(acc1[nt][2] * scale);
                    s_q[r1 * SQ + cl + 1] = tf32r(acc1[nt][3] * scale);
                } else if (sect == 1) {
                    s_k[r0 * SK + cl]     = tf32r(acc1[nt][0]);
                    s_k[r0 * SK + cl + 1] = tf32r(acc1[nt][1]);
                    s_k[r1 * SK + cl]     = tf32r(acc1[nt][2]);
                    s_k[r1 * SK + cl + 1] = tf32r(acc1[nt][3]);
                } else {
                    s_v[r0 * SV + cl]     = tf32r(acc1[nt][0]);
                    s_v[r0 * SV + cl + 1] = tf32r(acc1[nt][1]);
                    s_v[r1 * SV + cl]     = tf32r(acc1[nt][2]);
                    s_v[r1 * SV + cl + 1] = tf32r(acc1[nt][3]);
                }
            }
        }
        __syncthreads();

        // ================= scores: S[64,64] = q @ k^T ======================
        {
            float sacc[4][4];
            #pragma unroll
            for (int nt = 0; nt < 4; nt++) {
                sacc[nt][0] = 0.f; sacc[nt][1] = 0.f; sacc[nt][2] = 0.f; sacc[nt][3] = 0.f;
            }
            #pragma unroll
            for (int kk = 0; kk < 4; kk++) {
                const int ks = kk * 8;
                uint32_t a0 = __float_as_uint(s_q[(m + g)     * SQ + ks + tg]);
                uint32_t a1 = __float_as_uint(s_q[(m + g + 8) * SQ + ks + tg]);
                uint32_t a2 = __float_as_uint(s_q[(m + g)     * SQ + ks + tg + 4]);
                uint32_t a3 = __float_as_uint(s_q[(m + g + 8) * SQ + ks + tg + 4]);
                #pragma unroll
                for (int nt = 0; nt < 4; nt++) {
                    const int n = grp * 32 + nt * 8 + g;
                    uint32_t b0 = __float_as_uint(s_k[n * SK + ks + tg]);
                    uint32_t b1 = __float_as_uint(s_k[n * SK + ks + tg + 4]);
                    mma8(sacc[nt], a0, a1, a2, a3, b0, b1);
                }
            }
            #pragma unroll
            for (int nt = 0; nt < 4; nt++) {
                int n = grp * 32 + nt * 8 + 2 * tg;
                s_at[(m + g)     * SA + n]     = sacc[nt][0];
                s_at[(m + g)     * SA + n + 1] = sacc[nt][1];
                s_at[(m + g + 8) * SA + n]     = sacc[nt][2];
                s_at[(m + g + 8) * SA + n + 1] = sacc[nt][3];
            }
        }
        __syncthreads();

        // ============ softmax (+bias) rows; 4 threads per row =============
        {
            const int r = tid >> 2, q4 = tid & 3;
            float mx = -1e30f;
            for (int j = q4; j < 49; j += 4) {
                float bi = (r < 49) ? s_bt[(int)s_ri[r * 49 + j] * 8 + h] : 0.f;
                float v = s_at[r * SA + j] + bi;
                s_at[r * SA + j] = v;
                mx = fmaxf(mx, v);
            }
            mx = fmaxf(mx, __shfl_xor_sync(0xffffffffu, mx, 1, 4));
            mx = fmaxf(mx, __shfl_xor_sync(0xffffffffu, mx, 2, 4));
            float sum = 0.f;
            for (int j = q4; j < 49; j += 4) {
                float e = __expf(s_at[r * SA + j] - mx);
                s_at[r * SA + j] = e;
                sum += e;
            }
            sum += __shfl_xor_sync(0xffffffffu, sum, 1, 4);
            sum += __shfl_xor_sync(0xffffffffu, sum, 2, 4);
            float rinv = 1.0f / sum;
            for (int j = q4; j < 49; j += 4)
                s_at[r * SA + j] = tf32r(s_at[r * SA + j] * rinv);
            for (int j = 49 + q4; j < 64; j += 4)   // mask padded key columns
                s_at[r * SA + j] = 0.f;
        }
        // stage proj_w rows [h*32 .. h*32+31] into s_w (overlap with softmax)
        #pragma unroll
        for (int i = 0; i < 8; i++) {
            int idx = tid + i * 256;            // 0..2047 float4
            int r = idx >> 6, c4 = idx & 63;
            const float4 v = *(const float4*)(proj_w + (size_t)(h * 32 + r) * 256 + c4 * 4);
            float4 o;
            o.x = tf32r(v.x); o.y = tf32r(v.y); o.z = tf32r(v.z); o.w = tf32r(v.w);
            *(float4*)(s_w + r * SWP + c4 * 4) = o;
        }
        __syncthreads();

        // ================= O_h[64,32] = P @ v ==============================
        {
            float oacc[2][4];
            oacc[0][0]=0.f; oacc[0][1]=0.f; oacc[0][2]=0.f; oacc[0][3]=0.f;
            oacc[1][0]=0.f; oacc[1][1]=0.f; oacc[1][2]=0.f; oacc[1][3]=0.f;
            #pragma unroll
            for (int kk = 0; kk < 8; kk++) {
                const int ks = kk * 8;
                uint32_t a0 = __float_as_uint(s_at[(m + g)     * SA + ks + tg]);
                uint32_t a1 = __float_as_uint(s_at[(m + g + 8) * SA + ks + tg]);
                uint32_t a2 = __float_as_uint(s_at[(m + g)     * SA + ks + tg + 4]);
                uint32_t a3 = __float_as_uint(s_at[(m + g + 8) * SA + ks + tg + 4]);
                #pragma unroll
                for (int nt = 0; nt < 2; nt++) {
                    const int n = grp * 16 + nt * 8 + g;
                    uint32_t b0 = __float_as_uint(s_v[(ks + tg)     * SV + n]);
                    uint32_t b1 = __float_as_uint(s_v[(ks + tg + 4) * SV + n]);
                    mma8(oacc[nt], a0, a1, a2, a3, b0, b1);
                }
            }
            // O_h -> s_q (q is dead), tf32-rounded, as A for proj
            #pragma unroll
            for (int nt = 0; nt < 2; nt++) {
                int n = grp * 16 + nt * 8 + 2 * tg;
                s_q[(m + g)     * SQ + n]     = tf32r(oacc[nt][0]);
                s_q[(m + g)     * SQ + n + 1] = tf32r(oacc[nt][1]);
                s_q[(m + g + 8) * SQ + n]     = tf32r(oacc[nt][2]);
                s_q[(m + g + 8) * SQ + n + 1] = tf32r(oacc[nt][3]);
            }
        }
        __syncthreads();

        // ======== proj rank-32 update: facc += O_h[64,32] @ Wp_h[32,256] ===
        {
            const int ncb = grp * 128;
            #pragma unroll
            for (int kk = 0; kk < 4; kk++) {
                const int ks = kk * 8;
                uint32_t a0 = __float_as_uint(s_q[(m + g)     * SQ + ks + tg]);
                uint32_t a1 = __float_as_uint(s_q[(m + g + 8) * SQ + ks + tg]);
                uint32_t a2 = __float_as_uint(s_q[(m + g)     * SQ + ks + tg + 4]);
                uint32_t a3 = __float_as_uint(s_q[(m + g + 8) * SQ + ks + tg + 4]);
                #pragma unroll
                for (int j = 0; j < 16; j++) {
                    const int n = ncb + j * 8 + g;
                    uint32_t b0 = __float_as_uint(s_w[(ks + tg)     * SWP + n]);
                    uint32_t b1 = __float_as_uint(s_w[(ks + tg + 4) * SWP + n]);
                    mma8(facc[j], a0, a1, a2, a3, b0, b1);
                }
            }
        }
    } // heads

    // ================= epilogue: + proj_b, store rows < 49 =================
    {
        const int ncb = grp * 128;
        float* ob = out + (size_t)b * (NTOK * DIMC);
        const int r0 = m + g, r1 = m + g + 8;
        #pragma unroll
        for (int j = 0; j < 16; j++) {
            const int c = ncb + j * 8 + 2 * tg;
            if (r0 < 49) {
                float2 v; v.x = facc[j][0] + s_pb[c]; v.y = facc[j][1] + s_pb[c + 1];
                *(float2*)(ob + r0 * 256 + c) = v;
            }
            if (r1 < 49) {
                float2 v; v.x = facc[j][2] + s_pb[c]; v.y = facc[j][3] + s_pb[c + 1];
                *(float2*)(ob + r1 * 256 + c) = v;
            }
        }
    }
}

extern "C" void kernel_launch(void* const* d_in, const int* in_sizes, int n_in,
                              void* d_out, int out_size) {
    (void)in_sizes; (void)n_in; (void)out_size;
    const float* x      = (const float*)d_in[0];
    const float* qkv_w  = (const float*)d_in[1];
    const float* proj_w = (const float*)d_in[2];
    const float* proj_b = (const float*)d_in[3];
    const float* bt     = (const float*)d_in[4];
    const int*   ri     = (const int*)d_in[5];
    float* out = (float*)d_out;

    cudaFuncSetAttribute(win_attn_kernel,
                         cudaFuncAttributeMaxDynamicSharedMemorySize, SMEM_BYTES);
    win_attn_kernel<<<4096, 256, SMEM_BYTES>>>(x, qkv_w, proj_w, proj_b, bt, ri, out);
}